// round 12
// baseline (speedup 1.0000x reference)
#include <cuda_runtime.h>

// SoftMSMLoss: soft-MSM DP, gamma=1, c=1, 512x512, B=64.
// Probability-domain wavefront (P = e^{-C} as per-element (mantissa, int exp)).
// 32 blocks x 256 threads; each thread owns 2 adjacent rows of problem A AND
// the same 2 rows of problem B (4 cells/step, 2 independent chains). 8-warp
// handoff chain (7 boundaries) cuts skew; packed-u32 boundary handoff.

#define TLEN 512
#define NWARPS 8
#define NBATCH 64
#define CHUNK 8
#define NSTEP 544
#define LOG2E 1.4426950408889634f
#define LN2 0.6931471805599453f
#define KCONST 0.36787944117144233f  // e^{-c}, c=1
#define SENT (-8192)
#define EXPBIAS 16384
#define GATE_T 1e-3f

__device__ float g_costs[NBATCH];
__device__ int g_done;

__device__ __forceinline__ float scale2(int d) {  // 2^d, d<=0, underflow->0
    int bb = 127 + d;
    bb = max(bb, 0);
    return __int_as_float(bb << 23);
}

__device__ __forceinline__ unsigned packp(float sv, int mi) {
    const unsigned frac = (__float_as_uint(sv) >> 7) & 0xFFFFu;
    return (frac << 16) | (unsigned)(mi + EXPBIAS);
}
__device__ __forceinline__ void unpackp(unsigned pk, float& sv, int& mi) {
    sv = __uint_as_float(0x3F800000u | ((pk & 0xFFFF0000u) >> 9));
    mi = (int)(pk & 0xFFFFu) - EXPBIAS;
}

struct PV { float sv; int mi; };

__device__ __forceinline__ PV cell(float svU, int miU, float svD, int miD,
                                   float svL, int miL, float xi, float dxa,
                                   float Ea, float EaK, float4 cv) {
    const float bm = xi - cv.x;
    const float matchp = (LOG2E * bm) * bm;
    const float Em = exp2f(-matchp);
    const float EmK = Em * KCONST;

    const float uu = dxa * bm;
    const float ul = -cv.y * bm;
    float selU = (uu > 0.0f) ? (EaK + EmK) : KCONST;
    float selL = (ul > 0.0f) ? (cv.w + EmK) : KCONST;
    if (fabsf(uu) < GATE_T || fabsf(ul) < GATE_T) {  // exact smooth gate
        const float wu = 0.5f + 0.5f * uu * rsqrtf(uu * uu + 1e-9f);
        selU = KCONST * exp2f(wu * __log2f(Ea + Em));
        const float wl = 0.5f + 0.5f * ul * rsqrtf(ul * ul + 1e-9f);
        selL = KCONST * exp2f(wl * __log2f(cv.z + Em));
    }

    const float tD = svD * Em;
    const float tU = svU * selU;
    const float tL = svL * selL;
    const int mh = max(miD, max(miU, miL));
    const float ssum = fmaf(tD, scale2(miD - mh),
                            fmaf(tU, scale2(miU - mh), tL * scale2(miL - mh)));
    const int sb = __float_as_int(ssum);
    PV r;
    r.sv = __int_as_float((sb & 0x007FFFFF) | 0x3F800000);
    r.mi = mh + ((sb >> 23) - 127);
    return r;
}

__global__ __launch_bounds__(256, 1) void soft_msm_kernel(
    const float* __restrict__ x, const float* __restrict__ y,
    float* __restrict__ out) {
    __shared__ float4 scolA[TLEN], scolB[TLEN];  // {y_j, dyb, Eb, K*Eb}
    __shared__ unsigned handA[NWARPS - 1][TLEN];
    __shared__ unsigned handB[NWARPS - 1][TLEN];
    __shared__ volatile int flags[NWARPS - 1];

    const int t = threadIdx.x;  // owns rows 2t, 2t+1 of problems A and B
    const int w = t >> 5;
    const int l = t & 31;
    const int pA = 2 * blockIdx.x;
    const int pB = pA + 1;
    const float* xA = x + pA * TLEN;
    const float* yA = y + pA * TLEN;
    const float* xB = x + pB * TLEN;
    const float* yB = y + pB * TLEN;

    if (t < NWARPS - 1) flags[t] = 0;
    for (int jj = t; jj < TLEN; jj += 256) {
        const float yva = yA[jj];
        const float yvb = yB[jj];
        if (jj > 0) {
            const float da = yva - yA[jj - 1];
            const float ea = exp2f(-LOG2E * da * da);
            scolA[jj] = make_float4(yva, da, ea, ea * KCONST);
            const float db = yvb - yB[jj - 1];
            const float eb = exp2f(-LOG2E * db * db);
            scolB[jj] = make_float4(yvb, db, eb, eb * KCONST);
        } else {
            scolA[jj] = make_float4(yva, 1e9f, 0.0f, 0.0f);
            scolB[jj] = make_float4(yvb, 1e9f, 0.0f, 0.0f);
        }
    }
    const int r0 = 2 * t, r1 = 2 * t + 1;
    const float xiA0 = xA[r0], xiA1 = xA[r1];
    const float xiB0 = xB[r0], xiB1 = xB[r1];
    float dxaA0, EaA0, EaA0K, dxaB0, EaB0, EaB0K;
    if (r0 > 0) {
        dxaA0 = xiA0 - xA[r0 - 1];
        EaA0 = exp2f(-LOG2E * dxaA0 * dxaA0);
        EaA0K = EaA0 * KCONST;
        dxaB0 = xiB0 - xB[r0 - 1];
        EaB0 = exp2f(-LOG2E * dxaB0 * dxaB0);
        EaB0K = EaB0 * KCONST;
    } else {
        dxaA0 = 1e9f; EaA0 = 0.0f; EaA0K = 0.0f;
        dxaB0 = 1e9f; EaB0 = 0.0f; EaB0K = 0.0f;
    }
    const float dxaA1 = xiA1 - xiA0;
    const float EaA1 = exp2f(-LOG2E * dxaA1 * dxaA1);
    const float EaA1K = EaA1 * KCONST;
    const float dxaB1 = xiB1 - xiB0;
    const float EaB1 = exp2f(-LOG2E * dxaB1 * dxaB1);
    const float EaB1K = EaB1 * KCONST;
    __syncthreads();

    float svA0 = 0.0f, svA1 = 0.0f, svB0 = 0.0f, svB1 = 0.0f;
    int miA0 = SENT, miA1 = SENT, miB0 = SENT, miB1 = SENT;
    float svDA = (t == 0) ? 1.0f : 0.0f, svDB = svDA;
    int miDA = (t == 0) ? 0 : SENT, miDB = miDA;
    const bool isT0 = (t == 0);
    const bool isCons = (l == 0) && (w > 0);
    const bool isProd = (l == 31) && (w < NWARPS - 1);
    int availS = 0;

#pragma unroll 4
    for (int s = 0; s < NSTEP; ++s) {
        if (w > 0 && s < TLEN && (s & (CHUNK - 1)) == 0) {
            int need = s + CHUNK;
            if (need > TLEN) need = TLEN;
            if (availS < need) {
                while ((availS = flags[w - 1]) < need) __nanosleep(20);
                __threadfence_block();
            }
        }

        float svUA = __shfl_up_sync(0xffffffffu, svA1, 1);
        int miUA = __shfl_up_sync(0xffffffffu, miA1, 1);
        float svUB = __shfl_up_sync(0xffffffffu, svB1, 1);
        int miUB = __shfl_up_sync(0xffffffffu, miB1, 1);
        const int j = s - l;
        const bool active = ((unsigned)j < (unsigned)TLEN);
        const int jc = active ? j : 0;
        if (isT0) {
            svUA = 0.0f; miUA = SENT;
            svUB = 0.0f; miUB = SENT;
        }
        if (isCons) {
            unpackp(handA[w - 1][jc], svUA, miUA);
            unpackp(handB[w - 1][jc], svUB, miUB);
        }
        const float dgAs = svDA; const int dgAm = miDA;
        svDA = svUA; miDA = miUA;
        const float dgBs = svDB; const int dgBm = miDB;
        svDB = svUB; miDB = miUB;

        const float4 cvA = scolA[jc];
        const float4 cvB = scolB[jc];

        const PV nA0 = cell(svUA, miUA, dgAs, dgAm, svA0, miA0,
                            xiA0, dxaA0, EaA0, EaA0K, cvA);
        const PV nB0 = cell(svUB, miUB, dgBs, dgBm, svB0, miB0,
                            xiB0, dxaB0, EaB0, EaB0K, cvB);
        const PV nA1 = cell(nA0.sv, nA0.mi, svA0, miA0, svA1, miA1,
                            xiA1, dxaA1, EaA1, EaA1K, cvA);
        const PV nB1 = cell(nB0.sv, nB0.mi, svB0, miB0, svB1, miB1,
                            xiB1, dxaB1, EaB1, EaB1K, cvB);
        if (active) {
            svA0 = nA0.sv; miA0 = nA0.mi;
            svA1 = nA1.sv; miA1 = nA1.mi;
            svB0 = nB0.sv; miB0 = nB0.mi;
            svB1 = nB1.sv; miB1 = nB1.mi;
        }

        if (isProd) {
            handA[w][jc] = packp(svA1, miA1);
            handB[w][jc] = packp(svB1, miB1);
        }
        if (isProd && active && ((j & (CHUNK - 1)) == CHUNK - 1)) {
            __threadfence_block();
            flags[w] = j + 1;
        }
    }

    if (t == 255) {  // row 511 of both problems
        g_costs[pA] = -((float)miA1 + __log2f(svA1)) * LN2;
        g_costs[pB] = -((float)miB1 + __log2f(svB1)) * LN2;
        __threadfence();
        const int old = atomicAdd(&g_done, 1);
        if (old == NBATCH / 2 - 1) {
            __threadfence();
            float v = 0.0f;
#pragma unroll
            for (int i = 0; i < NBATCH; ++i) v += g_costs[i];
            out[0] = v * (1.0f / (float)NBATCH);
            atomicExch(&g_done, 0);
        }
    }
}

extern "C" void kernel_launch(void* const* d_in, const int* in_sizes, int n_in,
                              void* d_out, int out_size) {
    const float* x = (const float*)d_in[0];
    const float* y = (const float*)d_in[1];
    float* out = (float*)d_out;
    soft_msm_kernel<<<NBATCH / 2, 256>>>(x, y, out);
}

// round 13
// speedup vs baseline: 1.7585x; 1.7585x over previous
#include <cuda_runtime.h>

// SoftMSMLoss: soft-MSM DP, gamma=1, c=1, 512x512, B=64.
// Probability-domain wavefront (P = e^{-C} as per-element (mantissa, int exp)),
// 64 blocks x 512 threads (16 warps, 1 row/thread). Padded column/handoff
// arrays eliminate all boundary clamps/selects; out-of-range steps compute
// harmless garbage on zero-probability sentinels. Packed-u32 handoff, CHUNK=4.

#define TLEN 512
#define NW 16
#define NBATCH 64
#define CHUNK 4
#define PAD 32
#define HLEN (TLEN + 2 * PAD)  // 576
#define NSTEP 543               // lane31 last real cell j=511 at s=542
#define LOG2E 1.4426950408889634f
#define LN2 0.6931471805599453f
#define KCONST 0.36787944117144233f  // e^{-c}, c=1
#define SENT (-8192)
#define EXPBIAS 16384
#define PACK_ZERO ((unsigned)(SENT + EXPBIAS))  // sv=1.0, mi=SENT
#define GATE_T 1e-3f

__device__ float g_costs[NBATCH];
__device__ int g_done;

__device__ __forceinline__ float scale2(int d) {  // 2^d, d<=0, underflow->0
    int bb = 127 + d;
    bb = max(bb, 0);
    return __int_as_float(bb << 23);
}
__device__ __forceinline__ unsigned packp(float sv, int mi) {
    const unsigned frac = (__float_as_uint(sv) >> 7) & 0xFFFFu;
    return (frac << 16) | (unsigned)(mi + EXPBIAS);
}
__device__ __forceinline__ void unpackp(unsigned pk, float& sv, int& mi) {
    sv = __uint_as_float(0x3F800000u | ((pk & 0xFFFF0000u) >> 9));
    mi = (int)(pk & 0xFFFFu) - EXPBIAS;
}

__global__ __launch_bounds__(512, 1) void soft_msm_kernel(
    const float* __restrict__ x, const float* __restrict__ y,
    float* __restrict__ out) {
    __shared__ float4 scol[HLEN];           // {y_j, dyb_j, Eb_j, K*Eb_j}
    __shared__ unsigned hand[NW - 1][HLEN];  // packed boundary rows
    __shared__ volatile int flags[NW - 1];

    const int t = threadIdx.x;  // row index
    const int w = t >> 5;
    const int l = t & 31;
    const int b = blockIdx.x;
    const float* xb = x + b * TLEN;
    const float* yb = y + b * TLEN;

    if (t < NW - 1) flags[t] = 0;
    // column constants + pads
    for (int i = t; i < HLEN; i += 512) {
        const int j = i - PAD;
        if (j > 0 && j < TLEN) {
            const float yv = yb[j];
            const float dyb = yv - yb[j - 1];
            const float eb = exp2f(-LOG2E * dyb * dyb);
            scol[i] = make_float4(yv, dyb, eb, eb * KCONST);
        } else if (j == 0) {
            scol[i] = make_float4(yb[0], 1e9f, 0.0f, 0.0f);
        } else {  // pad: benign finite values
            scol[i] = make_float4(0.0f, 2.0f, 0.5f, 0.5f * KCONST);
        }
    }
    // handoff pads (low pad read at j<0; high pad read at j>511)
    for (int i = t; i < (NW - 1) * 2 * PAD; i += 512) {
        const int ww = i / (2 * PAD);
        const int kk = i % (2 * PAD);
        const int idx = (kk < PAD) ? kk : (HLEN - 2 * PAD + kk);
        hand[ww][idx] = PACK_ZERO;
    }
    const float xi = xb[t];
    float myDxa, myEa, myEaK;
    if (t > 0) {
        myDxa = xi - xb[t - 1];
        myEa = exp2f(-LOG2E * myDxa * myDxa);
        myEaK = myEa * KCONST;
    } else {
        myDxa = 1e9f;
        myEa = 0.0f;
        myEaK = 0.0f;
    }
    __syncthreads();

    float svC = 0.0f;  // own P(row, j-1)
    int miC = SENT;
    float svD = (t == 0) ? 1.0f : 0.0f;  // rolling up -> diag
    int miD_ = (t == 0) ? 0 : SENT;
    const bool isT0 = (t == 0);
    const bool isCons = (l == 0) && (w > 0);
    const bool isProd = (l == 31) && (w < NW - 1);
    int availS = 0;

#pragma unroll 8
    for (int s = 0; s < NSTEP; ++s) {
        if (w > 0 && (s & (CHUNK - 1)) == 0 && s < TLEN) {
            const int need = s + CHUNK;  // <= 512 (producer publishes 512)
            if (availS < need) {
                while ((availS = flags[w - 1]) < need) __nanosleep(20);
                __threadfence_block();
            }
        }

        float svU = __shfl_up_sync(0xffffffffu, svC, 1);
        int miU = __shfl_up_sync(0xffffffffu, miC, 1);
        const int j = s - l;  // may be out of [0,512) -> padded, harmless
        if (isT0) { svU = 0.0f; miU = SENT; }
        if (isCons) unpackp(hand[w - 1][j + PAD], svU, miU);
        const float dgS = svD;
        const int dgM = miD_;
        svD = svU;
        miD_ = miU;

        const float4 cv = scol[j + PAD];
        const float bm = xi - cv.x;
        const float matchp = (LOG2E * bm) * bm;
        const float Em = exp2f(-matchp);
        const float EmK = Em * KCONST;

        const float uu = myDxa * bm;
        const float ul = -cv.y * bm;
        float selU = (uu > 0.0f) ? (myEaK + EmK) : KCONST;
        float selL = (ul > 0.0f) ? (cv.w + EmK) : KCONST;
        if (fminf(fabsf(uu), fabsf(ul)) < GATE_T) {  // exact gate, rare
            const float wu = 0.5f + 0.5f * uu * rsqrtf(uu * uu + 1e-9f);
            selU = KCONST * exp2f(wu * __log2f(myEa + Em));
            const float wl = 0.5f + 0.5f * ul * rsqrtf(ul * ul + 1e-9f);
            selL = KCONST * exp2f(wl * __log2f(cv.z + Em));
        }

        const float tD = dgS * Em;
        const float tU = svU * selU;
        const float tL = svC * selL;
        const int mh = max(dgM, max(miU, miC));
        const float ssum =
            fmaf(tD, scale2(dgM - mh),
                 fmaf(tU, scale2(miU - mh), tL * scale2(miC - mh)));
        const int sb = __float_as_int(ssum);
        svC = __int_as_float((sb & 0x007FFFFF) | 0x3F800000);
        miC = mh + ((sb >> 23) - 127);

        if (isProd) hand[w][j + PAD] = packp(svC, miC);
        if (isProd && ((j & (CHUNK - 1)) == CHUNK - 1)) {
            __threadfence_block();
            flags[w] = j + 1;
        }
    }

    if (t == TLEN - 1) {  // last real cell computed at s=542: C(511,511)
        g_costs[b] = -((float)miC + __log2f(svC)) * LN2;
        __threadfence();
        const int old = atomicAdd(&g_done, 1);
        if (old == NBATCH - 1) {
            __threadfence();
            float v = 0.0f;
#pragma unroll
            for (int i = 0; i < NBATCH; ++i) v += g_costs[i];
            out[0] = v * (1.0f / (float)NBATCH);
            atomicExch(&g_done, 0);
        }
    }
}

extern "C" void kernel_launch(void* const* d_in, const int* in_sizes, int n_in,
                              void* d_out, int out_size) {
    const float* x = (const float*)d_in[0];
    const float* y = (const float*)d_in[1];
    float* out = (float*)d_out;
    soft_msm_kernel<<<NBATCH, 512>>>(x, y, out);
}